// round 16
// baseline (speedup 1.0000x reference)
#include <cuda_runtime.h>
#include <cuda_fp16.h>
#include <cstdint>
#include <cstddef>

#define B_SZ   4
#define T_LEN  512
#define S_LEN  4096
#define HID    1024
#define NH     16
#define HD     64
#define NBH    (B_SZ * NH)

// ---------------------------------------------------------------------------
// helpers
// ---------------------------------------------------------------------------
__device__ __forceinline__ uint32_t smem_u32(const void* p) {
    uint32_t a;
    asm("{ .reg .u64 t; cvta.to.shared.u64 t, %1; cvt.u32.u64 %0, t; }" : "=r"(a) : "l"(p));
    return a;
}
// 64B-row tile swizzle (K-major tiles)
__device__ __forceinline__ uint32_t swzoff(int row, int chunk) {
    const int v = (row & 3) ^ ((row >> 2) & 1);
    return (uint32_t)(row * 64 + (((chunk ^ v) & 3) << 4));
}
__device__ __forceinline__ void cpa16(uint32_t dst, const void* src) {
    asm volatile("cp.async.cg.shared.global [%0], [%1], 16;" :: "r"(dst), "l"(src));
}
#define CP_COMMIT() asm volatile("cp.async.commit_group;" ::: "memory")
#define CP_WAIT(n)  asm volatile("cp.async.wait_group %0;" :: "n"(n) : "memory")

__device__ __forceinline__ void ldsm4(uint32_t* r, uint32_t a) {
    asm volatile("ldmatrix.sync.aligned.m8n8.x4.shared.b16 {%0,%1,%2,%3}, [%4];"
                 : "=r"(r[0]), "=r"(r[1]), "=r"(r[2]), "=r"(r[3]) : "r"(a));
}
__device__ __forceinline__ void ldsm4t(uint32_t* r, uint32_t a) {
    asm volatile("ldmatrix.sync.aligned.m8n8.x4.trans.shared.b16 {%0,%1,%2,%3}, [%4];"
                 : "=r"(r[0]), "=r"(r[1]), "=r"(r[2]), "=r"(r[3]) : "r"(a));
}
__device__ __forceinline__ void mma_f16(float* d, const uint32_t* a, const uint32_t* b) {
    asm volatile("mma.sync.aligned.m16n8k16.row.col.f32.f16.f16.f32 "
                 "{%0,%1,%2,%3}, {%4,%5,%6,%7}, {%8,%9}, {%0,%1,%2,%3};"
                 : "+f"(d[0]), "+f"(d[1]), "+f"(d[2]), "+f"(d[3])
                 : "r"(a[0]), "r"(a[1]), "r"(a[2]), "r"(a[3]), "r"(b[0]), "r"(b[1]));
}
__device__ __forceinline__ void split2h(float v, __half& h, __half& l) {
    h = __float2half_rn(v);
    l = __float2half_rn(v - __half2float(h));
}

// Load a [ROWS x 32] fp16 tile (row stride = stride elems) into swizzled SMEM
template<int ROWS>
__device__ __forceinline__ void load_stage(uint32_t sbuf, const __half* g,
                                           int stride, int tid) {
    #pragma unroll
    for (int i = tid; i < ROWS * 4; i += 256) {
        const int row = i >> 2, ch = i & 3;
        cpa16(sbuf + swzoff(row, ch), g + (size_t)row * stride + ch * 8);
    }
}
// Load a [32 x 64] fp16 tile (128B rows, chunk-XOR swizzle) for trans-B (V)
__device__ __forceinline__ void load_vtile(uint32_t sbuf, const __half* g,
                                           int stride, int tid) {
    if (tid < 256) {
        const int row = tid >> 3, ch = tid & 7;
        cpa16(sbuf + (uint32_t)(row * 128 + (((ch ^ row) & 7) << 4)),
              g + (size_t)row * stride + ch * 8);
    }
}

// One 32-k stage, A single + B hi/lo, 2 products (Q projection).
__device__ __forceinline__ void stage_compute2(uint32_t sA,
                                               uint32_t sBh, uint32_t sBl,
                                               int wmr, int wnr, int lane,
                                               float (*acc)[4][4]) {
    const int l7 = lane & 7, l8 = (lane >> 3) & 1, l16 = (lane >> 4) & 1;
    const int arow = wmr + l7 + l8 * 8;
    const int brow = wnr + l16 * 8 + l7;
    #pragma unroll
    for (int ks = 0; ks < 2; ks++) {
        uint32_t ah[4][4], bh[2][4], bl[2][4];
        #pragma unroll
        for (int mi = 0; mi < 4; mi++)
            ldsm4(ah[mi], sA + swzoff(arow + mi * 16, ks * 2 + l16));
        #pragma unroll
        for (int p = 0; p < 2; p++) {
            const uint32_t off = swzoff(brow + p * 16, ks * 2 + l8);
            ldsm4(bh[p], sBh + off);
            ldsm4(bl[p], sBl + off);
        }
        #pragma unroll
        for (int mi = 0; mi < 4; mi++)
            #pragma unroll
            for (int nj = 0; nj < 4; nj++) {
                mma_f16(acc[mi][nj], ah[mi], &bh[nj >> 1][(nj & 1) * 2]);
                mma_f16(acc[mi][nj], ah[mi], &bl[nj >> 1][(nj & 1) * 2]);
            }
    }
}

// One 32-k stage, A single + B single, 1 product (K/V/O projections, scores).
__device__ __forceinline__ void stage_compute1(uint32_t sA, uint32_t sB,
                                               int wmr, int wnr, int lane,
                                               float (*acc)[4][4]) {
    const int l7 = lane & 7, l8 = (lane >> 3) & 1, l16 = (lane >> 4) & 1;
    const int arow = wmr + l7 + l8 * 8;
    const int brow = wnr + l16 * 8 + l7;
    #pragma unroll
    for (int ks = 0; ks < 2; ks++) {
        uint32_t ah[4][4], bh[2][4];
        #pragma unroll
        for (int mi = 0; mi < 4; mi++)
            ldsm4(ah[mi], sA + swzoff(arow + mi * 16, ks * 2 + l16));
        #pragma unroll
        for (int p = 0; p < 2; p++)
            ldsm4(bh[p], sB + swzoff(brow + p * 16, ks * 2 + l8));
        #pragma unroll
        for (int mi = 0; mi < 4; mi++)
            #pragma unroll
            for (int nj = 0; nj < 4; nj++)
                mma_f16(acc[mi][nj], ah[mi], &bh[nj >> 1][(nj & 1) * 2]);
    }
}

// One 32-k PV stage: A = E single (K-major, MI m-frags), B = V via ldmatrix.trans
template<int MI>
__device__ __forceinline__ void pv_stage1(uint32_t sA, uint32_t sB,
                                          int wmr, int wnr, int lane,
                                          float (*acc)[4][4]) {
    const int l7 = lane & 7, l8 = (lane >> 3) & 1, l16 = (lane >> 4) & 1;
    const int arow = wmr + l7 + l8 * 8;
    const int g = lane >> 3, q = lane & 7;
    #pragma unroll
    for (int ks = 0; ks < 2; ks++) {
        uint32_t ah[MI][4];
        #pragma unroll
        for (int mi = 0; mi < MI; mi++)
            ldsm4(ah[mi], sA + swzoff(arow + mi * 16, ks * 2 + l16));
        #pragma unroll
        for (int half = 0; half < 2; half++) {
            const int r = ks * 16 + (g & 1) * 8 + q;
            const int cb = ((wnr + half * 16) >> 3) + (g >> 1);
            const uint32_t off = (uint32_t)(r * 128 + (((cb ^ r) & 7) << 4));
            uint32_t bh4[4];
            ldsm4t(bh4, sB + off);
            #pragma unroll
            for (int mi = 0; mi < MI; mi++)
                #pragma unroll
                for (int u = 0; u < 2; u++)
                    mma_f16(acc[mi][half * 2 + u], ah[mi], &bh4[u * 2]);
        }
    }
}

// ---------------- scratch ----------------
__device__ __half g_qh[2048 * HID];
__device__ __half g_kh[16384 * HID];
__device__ __half g_vh[16384 * HID];
__device__ __half g_wqh[HID * HID], g_wql[HID * HID];
__device__ __half g_wkh[HID * HID];
__device__ __half g_wvh[HID * HID];
__device__ __half g_woh[HID * HID];
__device__ __half g_Qh[2048 * HID];
__device__ __half g_Kh[16384 * HID];
__device__ __half g_Vh[16384 * HID];
__device__ __half g_E[(size_t)NBH * T_LEN * S_LEN];     // exp(score-4), fp16
__device__ float  g_ps[(size_t)NBH * T_LEN * 32];       // per-block partial row sums
__device__ float  g_rs[NBH * T_LEN];                    // row sums
__device__ __half g_ah[2048 * HID];

// ---------------- fused conversions ----------------
// q: blocks [0,4096)  k: [4096,36864)  v: [36864,69632)
__global__ __launch_bounds__(256)
void conv_h_all(const float* __restrict__ Xq, const float* __restrict__ Xk,
                const float* __restrict__ Xv, __half* __restrict__ Hq,
                __half* __restrict__ Hk, __half* __restrict__ Hv) {
    const int bid = blockIdx.x;
    const float* X;
    __half* H;
    size_t u;
    if (bid < 4096)       { X = Xq; H = Hq; u = (size_t)bid * 256 + threadIdx.x; }
    else if (bid < 36864) { X = Xk; H = Hk; u = (size_t)(bid - 4096) * 256 + threadIdx.x; }
    else                  { X = Xv; H = Hv; u = (size_t)(bid - 36864) * 256 + threadIdx.x; }
    float2 v = reinterpret_cast<const float2*>(X)[u];
    reinterpret_cast<__half2*>(H)[u] =
        __halves2half2(__float2half_rn(v.x), __float2half_rn(v.y));
}
// z selects {0:Wq(hi+lo), 1:Wk, 2:Wv, 3:Wo}
__global__ __launch_bounds__(256)
void conv_wT_all(const float* __restrict__ Wq, const float* __restrict__ Wk,
                 const float* __restrict__ Wv, const float* __restrict__ Wo,
                 __half* __restrict__ WqH, __half* __restrict__ WqL,
                 __half* __restrict__ WkH, __half* __restrict__ WvH,
                 __half* __restrict__ WoH) {
    __shared__ float t[32][33];
    const int z = blockIdx.z;
    const float* W = (z == 0) ? Wq : (z == 1) ? Wk : (z == 2) ? Wv : Wo;
    __half* WTh    = (z == 0) ? WqH : (z == 1) ? WkH : (z == 2) ? WvH : WoH;
    __half* WTl    = (z == 0) ? WqL : nullptr;
    const int k0 = blockIdx.x * 32, n0 = blockIdx.y * 32;
    const int tx = threadIdx.x, ty = threadIdx.y;
    for (int r = ty; r < 32; r += 8) t[r][tx] = W[(size_t)(k0 + r) * HID + n0 + tx];
    __syncthreads();
    for (int r = ty; r < 32; r += 8) {
        __half h, l;
        split2h(t[tx][r], h, l);
        WTh[(size_t)(n0 + r) * HID + k0 + tx] = h;
        if (WTl) WTl[(size_t)(n0 + r) * HID + k0 + tx] = l;
    }
}

// ---------------- Q projection (2-product weights, single fp16 out, *0.125) ----------------
__global__ __launch_bounds__(256)
void proj2q(const __half* __restrict__ A,
            const __half* __restrict__ Bh, const __half* __restrict__ Bl,
            const float* __restrict__ bias, __half* __restrict__ outH) {
    extern __shared__ __align__(128) char sm[];
    const uint32_t sb = smem_u32(sm);
    const int tid = threadIdx.x, lane = tid & 31, w = tid >> 5;
    const int wmr = (w & 1) * 64, wnr = (w >> 1) * 32;
    const int n0 = blockIdx.x * 128, m0 = blockIdx.y * 128;
    const __half* gA  = A + (size_t)m0 * HID;
    const __half* gBh = Bh + (size_t)n0 * HID;
    const __half* gBl = Bl + (size_t)n0 * HID;

#define PJ_LOAD(st, ko) do {                                \
    const uint32_t b_ = sb + ((st) % 3) * 24576;            \
    load_stage<128>(b_ + 0,     gA  + (ko), HID, tid);      \
    load_stage<128>(b_ + 8192,  gBh + (ko), HID, tid);      \
    load_stage<128>(b_ + 16384, gBl + (ko), HID, tid);      \
    CP_COMMIT();                                            \
  } while (0)

    float acc[4][4][4] = {};
    PJ_LOAD(0, 0);
    PJ_LOAD(1, 32);
    const int NST = HID / 32;
    for (int s = 0; s < NST; s++) {
        if (s + 2 < NST) { PJ_LOAD(s + 2, (s + 2) * 32); CP_WAIT(2); }
        else if (s + 1 < NST) { CP_WAIT(1); }
        else { CP_WAIT(0); }
        __syncthreads();
        const uint32_t cur = sb + (s % 3) * 24576;
        stage_compute2(cur, cur + 8192, cur + 16384, wmr, wnr, lane, acc);
        __syncthreads();
    }
#undef PJ_LOAD

    const int mq = lane >> 2, nq = (lane & 3) * 2;
    #pragma unroll
    for (int mi = 0; mi < 4; mi++)
        #pragma unroll
        for (int half = 0; half < 2; half++) {
            const int m = m0 + wmr + mi * 16 + mq + half * 8;
            #pragma unroll
            for (int nj = 0; nj < 4; nj++) {
                const int n = n0 + wnr + nj * 8 + nq;
                float v0 = (acc[mi][nj][half * 2 + 0] + bias[n]) * 0.125f;
                float v1 = (acc[mi][nj][half * 2 + 1] + bias[n + 1]) * 0.125f;
                *(__half2*)(outH + (size_t)m * HID + n) =
                    __halves2half2(__float2half_rn(v0), __float2half_rn(v1));
            }
        }
}

// ---------------- K/O projection (1-product) ----------------
// MODE 1: O (bias, fp32 out)  2: K (bias+seg, fp16 out)
template<int MODE>
__global__ __launch_bounds__(256)
void proj1(const __half* __restrict__ A, const __half* __restrict__ B,
           const float* __restrict__ bias, const int* __restrict__ segids,
           const float* __restrict__ seg_emb, float* __restrict__ outF,
           __half* __restrict__ outH) {
    extern __shared__ __align__(128) char sm[];
    const uint32_t sb = smem_u32(sm);
    const int tid = threadIdx.x, lane = tid & 31, w = tid >> 5;
    const int wmr = (w & 1) * 64, wnr = (w >> 1) * 32;
    const int n0 = blockIdx.x * 128, m0 = blockIdx.y * 128;
    const __half* gA = A + (size_t)m0 * HID;
    const __half* gB = B + (size_t)n0 * HID;

#define P1_LOAD(st, ko) do {                                \
    const uint32_t b_ = sb + ((st) % 3) * 16384;            \
    load_stage<128>(b_ + 0,    gA + (ko), HID, tid);        \
    load_stage<128>(b_ + 8192, gB + (ko), HID, tid);        \
    CP_COMMIT();                                            \
  } while (0)

    float acc[4][4][4] = {};
    P1_LOAD(0, 0);
    P1_LOAD(1, 32);
    const int NST = HID / 32;
    for (int s = 0; s < NST; s++) {
        if (s + 2 < NST) { P1_LOAD(s + 2, (s + 2) * 32); CP_WAIT(2); }
        else if (s + 1 < NST) { CP_WAIT(1); }
        else { CP_WAIT(0); }
        __syncthreads();
        const uint32_t cur = sb + (s % 3) * 16384;
        stage_compute1(cur, cur + 8192, wmr, wnr, lane, acc);
        __syncthreads();
    }
#undef P1_LOAD

    const int mq = lane >> 2, nq = (lane & 3) * 2;
    #pragma unroll
    for (int mi = 0; mi < 4; mi++)
        #pragma unroll
        for (int half = 0; half < 2; half++) {
            const int m = m0 + wmr + mi * 16 + mq + half * 8;
            const int sid = (MODE == 2) ? segids[m] : 0;
            #pragma unroll
            for (int nj = 0; nj < 4; nj++) {
                const int n = n0 + wnr + nj * 8 + nq;
                float v0 = acc[mi][nj][half * 2 + 0] + bias[n];
                float v1 = acc[mi][nj][half * 2 + 1] + bias[n + 1];
                if (MODE == 2) {
                    v0 += seg_emb[(size_t)sid * HID + n];
                    v1 += seg_emb[(size_t)sid * HID + n + 1];
                }
                if (MODE != 1) {
                    *(__half2*)(outH + (size_t)m * HID + n) =
                        __halves2half2(__float2half_rn(v0), __float2half_rn(v1));
                } else {
                    *(float2*)(outF + (size_t)m * HID + n) = make_float2(v0, v1);
                }
            }
        }
}

// ---------------- fused scores_exp + V projection ----------------
// blocks [0,8192): scores+exp   blocks [8192,9216): V projection (1-product)
__global__ __launch_bounds__(256)
void score_v(const __half* __restrict__ Qh, const __half* __restrict__ Kh,
             const int* __restrict__ amask, __half* __restrict__ E,
             float* __restrict__ gps,
             const __half* __restrict__ Av, const __half* __restrict__ Bv,
             const float* __restrict__ biasv, __half* __restrict__ Vout) {
    extern __shared__ __align__(128) char sm[];
    __shared__ float psum[128][4];
    const uint32_t sb = smem_u32(sm);
    const int tid = threadIdx.x, lane = tid & 31, w = tid >> 5;
    const int bid = blockIdx.x;
    const int wmr = (w & 1) * 64, wnr = (w >> 1) * 32;
    const int mq = lane >> 2, nq = (lane & 3) * 2;

    if (bid < 8192) {
        // ---- scores + exp ----
        const int s0 = (bid & 31) * 128, t0 = ((bid >> 5) & 3) * 128, bh = bid >> 7;
        const int b = bh >> 4, h = bh & 15;
        const __half* gA = Qh + (size_t)(b * T_LEN + t0) * HID + h * HD;
        const __half* gB = Kh + (size_t)(b * S_LEN + s0) * HID + h * HD;

        float acc[4][4][4] = {};
        load_stage<128>(sb + 0,    gA, HID, tid);
        load_stage<128>(sb + 8192, gB, HID, tid);
        CP_COMMIT();
        load_stage<128>(sb + 16384, gA + 32, HID, tid);
        load_stage<128>(sb + 24576, gB + 32, HID, tid);
        CP_COMMIT();
        for (int s = 0; s < 2; s++) {
            if (s == 0) CP_WAIT(1);
            else CP_WAIT(0);
            __syncthreads();
            const uint32_t cur = sb + s * 16384;
            stage_compute1(cur, cur + 8192, wmr, wnr, lane, acc);
            __syncthreads();
        }

        __half* dstB = E + (size_t)bh * T_LEN * S_LEN;
        #pragma unroll
        for (int mi = 0; mi < 4; mi++)
            #pragma unroll
            for (int half = 0; half < 2; half++) {
                const int t = t0 + wmr + mi * 16 + mq + half * 8;
                float rsum = 0.f;
                #pragma unroll
                for (int nj = 0; nj < 4; nj++) {
                    const int sidx = s0 + wnr + nj * 8 + nq;
                    float e0 = (amask[b * S_LEN + sidx] == 0) ? 0.f
                               : __expf(acc[mi][nj][half * 2 + 0] - 4.f);
                    float e1 = (amask[b * S_LEN + sidx + 1] == 0) ? 0.f
                               : __expf(acc[mi][nj][half * 2 + 1] - 4.f);
                    rsum += e0 + e1;
                    __half2 h2;
                    h2.x = __float2half_rn(e0);
                    h2.y = __float2half_rn(e1);
                    *(__half2*)(dstB + (size_t)t * S_LEN + sidx) = h2;
                }
                rsum += __shfl_xor_sync(0xFFFFFFFFu, rsum, 1);
                rsum += __shfl_xor_sync(0xFFFFFFFFu, rsum, 2);
                if ((lane & 3) == 0)
                    psum[wmr + mi * 16 + half * 8 + mq][w >> 1] = rsum;
            }
        __syncthreads();
        if (tid < 128) {
            const float tot = psum[tid][0] + psum[tid][1] + psum[tid][2] + psum[tid][3];
            gps[((size_t)bh * T_LEN + t0 + tid) * 32 + (bid & 31)] = tot;
        }
    } else {
        // ---- V projection (1-product, 3-stage) ----
        const int q = bid - 8192;
        const int n0 = (q & 7) * 128, m0 = (q >> 3) * 128;
        const __half* gA = Av + (size_t)m0 * HID;
        const __half* gB = Bv + (size_t)n0 * HID;

#define PV_LOADW(st, ko) do {                               \
    const uint32_t b_ = sb + ((st) % 3) * 16384;            \
    load_stage<128>(b_ + 0,    gA + (ko), HID, tid);        \
    load_stage<128>(b_ + 8192, gB + (ko), HID, tid);        \
    CP_COMMIT();                                            \
  } while (0)

        float acc[4][4][4] = {};
        PV_LOADW(0, 0);
        PV_LOADW(1, 32);
        const int NST = HID / 32;
        for (int s = 0; s < NST; s++) {
            if (s + 2 < NST) { PV_LOADW(s + 2, (s + 2) * 32); CP_WAIT(2); }
            else if (s + 1 < NST) { CP_WAIT(1); }
            else { CP_WAIT(0); }
            __syncthreads();
            const uint32_t cur = sb + (s % 3) * 16384;
            stage_compute1(cur, cur + 8192, wmr, wnr, lane, acc);
            __syncthreads();
        }
#undef PV_LOADW

        #pragma unroll
        for (int mi = 0; mi < 4; mi++)
            #pragma unroll
            for (int half = 0; half < 2; half++) {
                const int m = m0 + wmr + mi * 16 + mq + half * 8;
                #pragma unroll
                for (int nj = 0; nj < 4; nj++) {
                    const int n = n0 + wnr + nj * 8 + nq;
                    float v0 = acc[mi][nj][half * 2 + 0] + biasv[n];
                    float v1 = acc[mi][nj][half * 2 + 1] + biasv[n + 1];
                    *(__half2*)(Vout + (size_t)m * HID + n) =
                        __halves2half2(__float2half_rn(v0), __float2half_rn(v1));
                }
            }
    }
}

// ---------------- row-sum reduce: rs[r] = sum of 32 partials ----------------
__global__ __launch_bounds__(256)
void rowsum_reduce(const float* __restrict__ gps, float* __restrict__ rs) {
    const int r = blockIdx.x * 256 + threadIdx.x;
    const float4* p = reinterpret_cast<const float4*>(gps + (size_t)r * 32);
    float s = 0.f;
    #pragma unroll
    for (int i = 0; i < 8; i++) {
        float4 v = p[i];
        s += v.x + v.y + v.z + v.w;
    }
    rs[r] = s;
}

// ---------------- fused pv + provenance ----------------
// blocks [0,256): P·V GEMM   blocks [256,16640): provenance head-mean
__global__ __launch_bounds__(256)
void attn_epi(const __half* __restrict__ E, const __half* __restrict__ Vh,
              const float* __restrict__ rs, __half* __restrict__ attH,
              float* __restrict__ out) {
    extern __shared__ __align__(128) char sm[];
    const uint32_t sb = smem_u32(sm);
    const int tid = threadIdx.x, lane = tid & 31, w = tid >> 5;
    const int bid = blockIdx.x;

    if (bid < 256) {
        // ---- P·V: C[128,64] per CTA, K=4096, normalized epilogue ----
        const int wmr = (w & 3) * 32, wnr = (w >> 2) * 32;
        const int bh = bid >> 2, b = bh >> 4, h = bh & 15;
        const int t0 = (bid & 3) * 128;
        const __half* gA = E + ((size_t)bh * T_LEN + t0) * S_LEN;
        const __half* gB = Vh + (size_t)(b * S_LEN) * HID + h * HD;

#define PV_LOAD(st, ko) do {                                              \
    const uint32_t b_ = sb + ((st) % 3) * 12288;                          \
    load_stage<128>(b_ + 0, gA + (ko), S_LEN, tid);                       \
    load_vtile(b_ + 8192, gB + (size_t)(ko) * HID, HID, tid);             \
    CP_COMMIT();                                                          \
  } while (0)

        float acc[2][4][4] = {};
        PV_LOAD(0, 0);
        PV_LOAD(1, 32);
        const int NST = S_LEN / 32;
        for (int s = 0; s < NST; s++) {
            if (s + 2 < NST) { PV_LOAD(s + 2, (s + 2) * 32); CP_WAIT(2); }
            else if (s + 1 < NST) { CP_WAIT(1); }
            else { CP_WAIT(0); }
            __syncthreads();
            const uint32_t cur = sb + (s % 3) * 12288;
            pv_stage1<2>(cur, cur + 8192, wmr, wnr, lane, acc);
            __syncthreads();
        }
#undef PV_LOAD

        const int mq = lane >> 2, nq = (lane & 3) * 2;
        #pragma unroll
        for (int mi = 0; mi < 2; mi++)
            #pragma unroll
            for (int half = 0; half < 2; half++) {
                const int t = t0 + wmr + mi * 16 + mq + half * 8;
                const float inv = 1.0f / rs[bh * T_LEN + t];
                const size_t mo = (size_t)(b * T_LEN + t) * HID + h * HD;
                #pragma unroll
                for (int nj = 0; nj < 4; nj++) {
                    const int n = wnr + nj * 8 + nq;
                    __half2 h2;
                    h2.x = __float2half_rn(acc[mi][nj][half * 2 + 0] * inv);
                    h2.y = __float2half_rn(acc[mi][nj][half * 2 + 1] * inv);
                    *(__half2*)(attH + mo + n) = h2;
                }
            }
    } else {
        // ---- provenance ----
        const size_t u = (size_t)(bid - 256) * 256 + tid;
        const int s2 = (int)(u & 2047);
        const int t  = (int)((u >> 11) & 511);
        const int b  = (int)(u >> 20);
        float s0 = 0.f, s1 = 0.f;
        #pragma unroll
        for (int h = 0; h < NH; h++) {
            const int bh = b * NH + h;
            const float inv = 1.0f / rs[bh * T_LEN + t];
            const size_t o = (((size_t)bh * T_LEN + t) * S_LEN) / 2 + s2;
            __half2 h2 = reinterpret_cast<const __half2*>(E)[o];
            s0 += __half2float(h2.x) * inv;
            s1 += __half2float(h2.y) * inv;
        }
        reinterpret_cast<float2*>(out)[u] = make_float2(s0 * (1.0f / NH), s1 * (1.0f / NH));
    }
}

// ---------------------------------------------------------------------------
extern "C" void kernel_launch(void* const* d_in, const int* in_sizes, int n_in,
                              void* d_out, int out_size) {
    const float* query  = (const float*)d_in[0];
    const float* key    = (const float*)d_in[1];
    const float* value  = (const float*)d_in[2];
    const int*   amask  = (const int*)d_in[3];
    const int*   segids = (const int*)d_in[4];
    const float* Wq = (const float*)d_in[5];
    const float* bq = (const float*)d_in[6];
    const float* Wk = (const float*)d_in[7];
    const float* bk = (const float*)d_in[8];
    const float* Wv = (const float*)d_in[9];
    const float* bv = (const float*)d_in[10];
    const float* Wo = (const float*)d_in[11];
    const float* bo = (const float*)d_in[12];
    const float* seg_emb = (const float*)d_in[13];
    float* out = (float*)d_out;

    __half *qh, *kh, *vh;
    __half *wqh, *wql, *wkh, *wvh, *woh;
    __half *Qh, *Kh, *Vh, *E, *ah;
    float *ps, *rs;
    cudaGetSymbolAddress((void**)&qh, g_qh);
    cudaGetSymbolAddress((void**)&kh, g_kh);
    cudaGetSymbolAddress((void**)&vh, g_vh);
    cudaGetSymbolAddress((void**)&wqh, g_wqh); cudaGetSymbolAddress((void**)&wql, g_wql);
    cudaGetSymbolAddress((void**)&wkh, g_wkh);
    cudaGetSymbolAddress((void**)&wvh, g_wvh);
    cudaGetSymbolAddress((void**)&woh, g_woh);
    cudaGetSymbolAddress((void**)&Qh, g_Qh);
    cudaGetSymbolAddress((void**)&Kh, g_Kh);
    cudaGetSymbolAddress((void**)&Vh, g_Vh);
    cudaGetSymbolAddress((void**)&E, g_E);
    cudaGetSymbolAddress((void**)&ps, g_ps);
    cudaGetSymbolAddress((void**)&rs, g_rs);
    cudaGetSymbolAddress((void**)&ah, g_ah);

    cudaFuncSetAttribute(proj2q, cudaFuncAttributeMaxDynamicSharedMemorySize, 73728);
    cudaFuncSetAttribute(proj1<1>, cudaFuncAttributeMaxDynamicSharedMemorySize, 49152);
    cudaFuncSetAttribute(proj1<2>, cudaFuncAttributeMaxDynamicSharedMemorySize, 49152);
    cudaFuncSetAttribute(score_v, cudaFuncAttributeMaxDynamicSharedMemorySize, 49152);
    cudaFuncSetAttribute(attn_epi, cudaFuncAttributeMaxDynamicSharedMemorySize, 36864);

    // fused conversions
    conv_h_all<<<69632, 256>>>(query, key, value, qh, kh, vh);
    conv_wT_all<<<dim3(32, 32, 4), dim3(32, 8)>>>(Wq, Wk, Wv, Wo, wqh, wql, wkh, wvh, woh);

    // Q and K projections
    proj2q<<<dim3(8, 16), 256, 73728>>>(qh, wqh, wql, bq, Qh);
    proj1<2><<<dim3(8, 128), 256, 49152>>>(kh, wkh, bk, segids, seg_emb, nullptr, Kh);

    // fused scores+exp and V projection (concurrent roles in one launch)
    score_v<<<9216, 256, 49152>>>(Qh, Kh, amask, E, ps, vh, wvh, bv, Vh);
    rowsum_reduce<<<NBH * T_LEN / 256, 256>>>(ps, rs);

    // fused P·V + provenance (concurrent roles in one launch)
    attn_epi<<<16640, 256, 36864>>>(E, Vh, rs, ah, out + (size_t)2048 * HID);

    // output projection -> d_out
    proj1<1><<<dim3(8, 16), 256, 49152>>>(ah, woh, bo, nullptr, nullptr, out, nullptr);
}

// round 17
// speedup vs baseline: 1.3483x; 1.3483x over previous
#include <cuda_runtime.h>
#include <cuda_fp16.h>
#include <cstdint>
#include <cstddef>

#define B_SZ   4
#define T_LEN  512
#define S_LEN  4096
#define HID    1024
#define NH     16
#define HD     64
#define NBH    (B_SZ * NH)

// ---------------------------------------------------------------------------
// helpers
// ---------------------------------------------------------------------------
__device__ __forceinline__ uint32_t smem_u32(const void* p) {
    uint32_t a;
    asm("{ .reg .u64 t; cvta.to.shared.u64 t, %1; cvt.u32.u64 %0, t; }" : "=r"(a) : "l"(p));
    return a;
}
// 64B-row tile swizzle (K-major tiles)
__device__ __forceinline__ uint32_t swzoff(int row, int chunk) {
    const int v = (row & 3) ^ ((row >> 2) & 1);
    return (uint32_t)(row * 64 + (((chunk ^ v) & 3) << 4));
}
__device__ __forceinline__ void cpa16(uint32_t dst, const void* src) {
    asm volatile("cp.async.cg.shared.global [%0], [%1], 16;" :: "r"(dst), "l"(src));
}
#define CP_COMMIT() asm volatile("cp.async.commit_group;" ::: "memory")
#define CP_WAIT(n)  asm volatile("cp.async.wait_group %0;" :: "n"(n) : "memory")

__device__ __forceinline__ void ldsm4(uint32_t* r, uint32_t a) {
    asm volatile("ldmatrix.sync.aligned.m8n8.x4.shared.b16 {%0,%1,%2,%3}, [%4];"
                 : "=r"(r[0]), "=r"(r[1]), "=r"(r[2]), "=r"(r[3]) : "r"(a));
}
__device__ __forceinline__ void ldsm4t(uint32_t* r, uint32_t a) {
    asm volatile("ldmatrix.sync.aligned.m8n8.x4.trans.shared.b16 {%0,%1,%2,%3}, [%4];"
                 : "=r"(r[0]), "=r"(r[1]), "=r"(r[2]), "=r"(r[3]) : "r"(a));
}
__device__ __forceinline__ void mma_f16(float* d, const uint32_t* a, const uint32_t* b) {
    asm volatile("mma.sync.aligned.m16n8k16.row.col.f32.f16.f16.f32 "
                 "{%0,%1,%2,%3}, {%4,%5,%6,%7}, {%8,%9}, {%0,%1,%2,%3};"
                 : "+f"(d[0]), "+f"(d[1]), "+f"(d[2]), "+f"(d[3])
                 : "r"(a[0]), "r"(a[1]), "r"(a[2]), "r"(a[3]), "r"(b[0]), "r"(b[1]));
}
__device__ __forceinline__ void split2h(float v, __half& h, __half& l) {
    h = __float2half_rn(v);
    l = __float2half_rn(v - __half2float(h));
}

// Load a [ROWS x 32] fp16 tile (row stride = stride elems) into swizzled SMEM
template<int ROWS>
__device__ __forceinline__ void load_stage(uint32_t sbuf, const __half* g,
                                           int stride, int tid) {
    #pragma unroll
    for (int i = tid; i < ROWS * 4; i += 256) {
        const int row = i >> 2, ch = i & 3;
        cpa16(sbuf + swzoff(row, ch), g + (size_t)row * stride + ch * 8);
    }
}
// Load a [32 x 64] fp16 tile (128B rows, chunk-XOR swizzle) for trans-B (V)
__device__ __forceinline__ void load_vtile(uint32_t sbuf, const __half* g,
                                           int stride, int tid) {
    if (tid < 256) {
        const int row = tid >> 3, ch = tid & 7;
        cpa16(sbuf + (uint32_t)(row * 128 + (((ch ^ row) & 7) << 4)),
              g + (size_t)row * stride + ch * 8);
    }
}

// One 32-k stage, A single + B hi/lo, 2 products (Q projection).
__device__ __forceinline__ void stage_compute2(uint32_t sA,
                                               uint32_t sBh, uint32_t sBl,
                                               int wmr, int wnr, int lane,
                                               float (*acc)[4][4]) {
    const int l7 = lane & 7, l8 = (lane >> 3) & 1, l16 = (lane >> 4) & 1;
    const int arow = wmr + l7 + l8 * 8;
    const int brow = wnr + l16 * 8 + l7;
    #pragma unroll
    for (int ks = 0; ks < 2; ks++) {
        uint32_t ah[4][4], bh[2][4], bl[2][4];
        #pragma unroll
        for (int mi = 0; mi < 4; mi++)
            ldsm4(ah[mi], sA + swzoff(arow + mi * 16, ks * 2 + l16));
        #pragma unroll
        for (int p = 0; p < 2; p++) {
            const uint32_t off = swzoff(brow + p * 16, ks * 2 + l8);
            ldsm4(bh[p], sBh + off);
            ldsm4(bl[p], sBl + off);
        }
        #pragma unroll
        for (int mi = 0; mi < 4; mi++)
            #pragma unroll
            for (int nj = 0; nj < 4; nj++) {
                mma_f16(acc[mi][nj], ah[mi], &bh[nj >> 1][(nj & 1) * 2]);
                mma_f16(acc[mi][nj], ah[mi], &bl[nj >> 1][(nj & 1) * 2]);
            }
    }
}

// One 32-k stage, A single + B single, 1 product (K/V/O projections, scores).
__device__ __forceinline__ void stage_compute1(uint32_t sA, uint32_t sB,
                                               int wmr, int wnr, int lane,
                                               float (*acc)[4][4]) {
    const int l7 = lane & 7, l8 = (lane >> 3) & 1, l16 = (lane >> 4) & 1;
    const int arow = wmr + l7 + l8 * 8;
    const int brow = wnr + l16 * 8 + l7;
    #pragma unroll
    for (int ks = 0; ks < 2; ks++) {
        uint32_t ah[4][4], bh[2][4];
        #pragma unroll
        for (int mi = 0; mi < 4; mi++)
            ldsm4(ah[mi], sA + swzoff(arow + mi * 16, ks * 2 + l16));
        #pragma unroll
        for (int p = 0; p < 2; p++)
            ldsm4(bh[p], sB + swzoff(brow + p * 16, ks * 2 + l8));
        #pragma unroll
        for (int mi = 0; mi < 4; mi++)
            #pragma unroll
            for (int nj = 0; nj < 4; nj++)
                mma_f16(acc[mi][nj], ah[mi], &bh[nj >> 1][(nj & 1) * 2]);
    }
}

// One 32-k PV stage: A = E single (K-major, MI m-frags), B = V via ldmatrix.trans
template<int MI>
__device__ __forceinline__ void pv_stage1(uint32_t sA, uint32_t sB,
                                          int wmr, int wnr, int lane,
                                          float (*acc)[4][4]) {
    const int l7 = lane & 7, l8 = (lane >> 3) & 1, l16 = (lane >> 4) & 1;
    const int arow = wmr + l7 + l8 * 8;
    const int g = lane >> 3, q = lane & 7;
    #pragma unroll
    for (int ks = 0; ks < 2; ks++) {
        uint32_t ah[MI][4];
        #pragma unroll
        for (int mi = 0; mi < MI; mi++)
            ldsm4(ah[mi], sA + swzoff(arow + mi * 16, ks * 2 + l16));
        #pragma unroll
        for (int half = 0; half < 2; half++) {
            const int r = ks * 16 + (g & 1) * 8 + q;
            const int cb = ((wnr + half * 16) >> 3) + (g >> 1);
            const uint32_t off = (uint32_t)(r * 128 + (((cb ^ r) & 7) << 4));
            uint32_t bh4[4];
            ldsm4t(bh4, sB + off);
            #pragma unroll
            for (int mi = 0; mi < MI; mi++)
                #pragma unroll
                for (int u = 0; u < 2; u++)
                    mma_f16(acc[mi][half * 2 + u], ah[mi], &bh4[u * 2]);
        }
    }
}

// ---------------- scratch ----------------
__device__ __half g_qh[2048 * HID];
__device__ __half g_kh[16384 * HID];
__device__ __half g_vh[16384 * HID];
__device__ __half g_wqh[HID * HID], g_wql[HID * HID];
__device__ __half g_wkh[HID * HID];
__device__ __half g_wvh[HID * HID];
__device__ __half g_woh[HID * HID];
__device__ __half g_Qh[2048 * HID];
__device__ __half g_Kh[16384 * HID];
__device__ __half g_Vh[16384 * HID];
__device__ __half g_E[(size_t)NBH * T_LEN * S_LEN];     // exp(score-4), fp16
__device__ float  g_ps[(size_t)NBH * T_LEN * 32];       // per-block partial row sums
__device__ float  g_rs[NBH * T_LEN];                    // row sums
__device__ __half g_ah[2048 * HID];

// ---------------- fused conversions (homogeneous roles) ----------------
__global__ __launch_bounds__(256)
void conv_h_all(const float* __restrict__ Xq, const float* __restrict__ Xk,
                const float* __restrict__ Xv, __half* __restrict__ Hq,
                __half* __restrict__ Hk, __half* __restrict__ Hv) {
    const int bid = blockIdx.x;
    const float* X;
    __half* H;
    size_t u;
    if (bid < 4096)       { X = Xq; H = Hq; u = (size_t)bid * 256 + threadIdx.x; }
    else if (bid < 36864) { X = Xk; H = Hk; u = (size_t)(bid - 4096) * 256 + threadIdx.x; }
    else                  { X = Xv; H = Hv; u = (size_t)(bid - 36864) * 256 + threadIdx.x; }
    float2 v = reinterpret_cast<const float2*>(X)[u];
    reinterpret_cast<__half2*>(H)[u] =
        __halves2half2(__float2half_rn(v.x), __float2half_rn(v.y));
}
__global__ __launch_bounds__(256)
void conv_wT_all(const float* __restrict__ Wq, const float* __restrict__ Wk,
                 const float* __restrict__ Wv, const float* __restrict__ Wo,
                 __half* __restrict__ WqH, __half* __restrict__ WqL,
                 __half* __restrict__ WkH, __half* __restrict__ WvH,
                 __half* __restrict__ WoH) {
    __shared__ float t[32][33];
    const int z = blockIdx.z;
    const float* W = (z == 0) ? Wq : (z == 1) ? Wk : (z == 2) ? Wv : Wo;
    __half* WTh    = (z == 0) ? WqH : (z == 1) ? WkH : (z == 2) ? WvH : WoH;
    __half* WTl    = (z == 0) ? WqL : nullptr;
    const int k0 = blockIdx.x * 32, n0 = blockIdx.y * 32;
    const int tx = threadIdx.x, ty = threadIdx.y;
    for (int r = ty; r < 32; r += 8) t[r][tx] = W[(size_t)(k0 + r) * HID + n0 + tx];
    __syncthreads();
    for (int r = ty; r < 32; r += 8) {
        __half h, l;
        split2h(t[tx][r], h, l);
        WTh[(size_t)(n0 + r) * HID + k0 + tx] = h;
        if (WTl) WTl[(size_t)(n0 + r) * HID + k0 + tx] = l;
    }
}

// ---------------- Q projection (2-product weights, single fp16 out, *0.125) ----------------
__global__ __launch_bounds__(256)
void proj2q(const __half* __restrict__ A,
            const __half* __restrict__ Bh, const __half* __restrict__ Bl,
            const float* __restrict__ bias, __half* __restrict__ outH) {
    extern __shared__ __align__(128) char sm[];
    const uint32_t sb = smem_u32(sm);
    const int tid = threadIdx.x, lane = tid & 31, w = tid >> 5;
    const int wmr = (w & 1) * 64, wnr = (w >> 1) * 32;
    const int n0 = blockIdx.x * 128, m0 = blockIdx.y * 128;
    const __half* gA  = A + (size_t)m0 * HID;
    const __half* gBh = Bh + (size_t)n0 * HID;
    const __half* gBl = Bl + (size_t)n0 * HID;

#define PJ_LOAD(st, ko) do {                                \
    const uint32_t b_ = sb + ((st) % 3) * 24576;            \
    load_stage<128>(b_ + 0,     gA  + (ko), HID, tid);      \
    load_stage<128>(b_ + 8192,  gBh + (ko), HID, tid);      \
    load_stage<128>(b_ + 16384, gBl + (ko), HID, tid);      \
    CP_COMMIT();                                            \
  } while (0)

    float acc[4][4][4] = {};
    PJ_LOAD(0, 0);
    PJ_LOAD(1, 32);
    const int NST = HID / 32;
    for (int s = 0; s < NST; s++) {
        if (s + 2 < NST) { PJ_LOAD(s + 2, (s + 2) * 32); CP_WAIT(2); }
        else if (s + 1 < NST) { CP_WAIT(1); }
        else { CP_WAIT(0); }
        __syncthreads();
        const uint32_t cur = sb + (s % 3) * 24576;
        stage_compute2(cur, cur + 8192, cur + 16384, wmr, wnr, lane, acc);
        __syncthreads();
    }
#undef PJ_LOAD

    const int mq = lane >> 2, nq = (lane & 3) * 2;
    #pragma unroll
    for (int mi = 0; mi < 4; mi++)
        #pragma unroll
        for (int half = 0; half < 2; half++) {
            const int m = m0 + wmr + mi * 16 + mq + half * 8;
            #pragma unroll
            for (int nj = 0; nj < 4; nj++) {
                const int n = n0 + wnr + nj * 8 + nq;
                float v0 = (acc[mi][nj][half * 2 + 0] + bias[n]) * 0.125f;
                float v1 = (acc[mi][nj][half * 2 + 1] + bias[n + 1]) * 0.125f;
                *(__half2*)(outH + (size_t)m * HID + n) =
                    __halves2half2(__float2half_rn(v0), __float2half_rn(v1));
            }
        }
}

// ---------------- merged K+V projection (homogeneous roles, one launch) ----------------
// grid (8, 256): y<128 -> K row-block y (bias+seg), y>=128 -> V row-block y-128 (bias)
__global__ __launch_bounds__(256)
void proj_kv(const __half* __restrict__ kh, const __half* __restrict__ vh,
             const __half* __restrict__ wkh, const __half* __restrict__ wvh,
             const float* __restrict__ bk, const float* __restrict__ bv,
             const int* __restrict__ segids, const float* __restrict__ seg_emb,
             __half* __restrict__ Kout, __half* __restrict__ Vout) {
    extern __shared__ __align__(128) char sm[];
    const uint32_t sb = smem_u32(sm);
    const int tid = threadIdx.x, lane = tid & 31, w = tid >> 5;
    const int wmr = (w & 1) * 64, wnr = (w >> 1) * 32;
    const int isK = (blockIdx.y < 128);
    const int m0 = (isK ? blockIdx.y : blockIdx.y - 128) * 128;
    const int n0 = blockIdx.x * 128;
    const __half* gA = (isK ? kh : vh) + (size_t)m0 * HID;
    const __half* gB = (isK ? wkh : wvh) + (size_t)n0 * HID;
    const float* bias = isK ? bk : bv;
    __half* outH = isK ? Kout : Vout;

#define P1_LOAD(st, ko) do {                                \
    const uint32_t b_ = sb + ((st) % 3) * 16384;            \
    load_stage<128>(b_ + 0,    gA + (ko), HID, tid);        \
    load_stage<128>(b_ + 8192, gB + (ko), HID, tid);        \
    CP_COMMIT();                                            \
  } while (0)

    float acc[4][4][4] = {};
    P1_LOAD(0, 0);
    P1_LOAD(1, 32);
    const int NST = HID / 32;
    for (int s = 0; s < NST; s++) {
        if (s + 2 < NST) { P1_LOAD(s + 2, (s + 2) * 32); CP_WAIT(2); }
        else if (s + 1 < NST) { CP_WAIT(1); }
        else { CP_WAIT(0); }
        __syncthreads();
        const uint32_t cur = sb + (s % 3) * 16384;
        stage_compute1(cur, cur + 8192, wmr, wnr, lane, acc);
        __syncthreads();
    }
#undef P1_LOAD

    const int mq = lane >> 2, nq = (lane & 3) * 2;
    #pragma unroll
    for (int mi = 0; mi < 4; mi++)
        #pragma unroll
        for (int half = 0; half < 2; half++) {
            const int m = m0 + wmr + mi * 16 + mq + half * 8;
            const int sid = isK ? segids[m] : 0;
            #pragma unroll
            for (int nj = 0; nj < 4; nj++) {
                const int n = n0 + wnr + nj * 8 + nq;
                float v0 = acc[mi][nj][half * 2 + 0] + bias[n];
                float v1 = acc[mi][nj][half * 2 + 1] + bias[n + 1];
                if (isK) {
                    v0 += seg_emb[(size_t)sid * HID + n];
                    v1 += seg_emb[(size_t)sid * HID + n + 1];
                }
                *(__half2*)(outH + (size_t)m * HID + n) =
                    __halves2half2(__float2half_rn(v0), __float2half_rn(v1));
            }
        }
}

// ---------------- O projection (1-product, fp32 out) ----------------
__global__ __launch_bounds__(256)
void proj_o(const __half* __restrict__ A, const __half* __restrict__ B,
            const float* __restrict__ bias, float* __restrict__ outF) {
    extern __shared__ __align__(128) char sm[];
    const uint32_t sb = smem_u32(sm);
    const int tid = threadIdx.x, lane = tid & 31, w = tid >> 5;
    const int wmr = (w & 1) * 64, wnr = (w >> 1) * 32;
    const int n0 = blockIdx.x * 128, m0 = blockIdx.y * 128;
    const __half* gA = A + (size_t)m0 * HID;
    const __half* gB = B + (size_t)n0 * HID;

#define PO_LOAD(st, ko) do {                                \
    const uint32_t b_ = sb + ((st) % 3) * 16384;            \
    load_stage<128>(b_ + 0,    gA + (ko), HID, tid);        \
    load_stage<128>(b_ + 8192, gB + (ko), HID, tid);        \
    CP_COMMIT();                                            \
  } while (0)

    float acc[4][4][4] = {};
    PO_LOAD(0, 0);
    PO_LOAD(1, 32);
    const int NST = HID / 32;
    for (int s = 0; s < NST; s++) {
        if (s + 2 < NST) { PO_LOAD(s + 2, (s + 2) * 32); CP_WAIT(2); }
        else if (s + 1 < NST) { CP_WAIT(1); }
        else { CP_WAIT(0); }
        __syncthreads();
        const uint32_t cur = sb + (s % 3) * 16384;
        stage_compute1(cur, cur + 8192, wmr, wnr, lane, acc);
        __syncthreads();
    }
#undef PO_LOAD

    const int mq = lane >> 2, nq = (lane & 3) * 2;
    #pragma unroll
    for (int mi = 0; mi < 4; mi++)
        #pragma unroll
        for (int half = 0; half < 2; half++) {
            const int m = m0 + wmr + mi * 16 + mq + half * 8;
            #pragma unroll
            for (int nj = 0; nj < 4; nj++) {
                const int n = n0 + wnr + nj * 8 + nq;
                float v0 = acc[mi][nj][half * 2 + 0] + bias[n];
                float v1 = acc[mi][nj][half * 2 + 1] + bias[n + 1];
                *(float2*)(outF + (size_t)m * HID + n) = make_float2(v0, v1);
            }
        }
}

// ---------------- scores+exp: E[bh,t,s] = exp(Q·K^T - 4), partial row sums ----------------
__global__ __launch_bounds__(256)
void scores_exp(const __half* __restrict__ Qh, const __half* __restrict__ Kh,
                const int* __restrict__ amask, __half* __restrict__ E,
                float* __restrict__ gps) {
    extern __shared__ __align__(128) char sm[];
    __shared__ float psum[128][4];
    const uint32_t sb = smem_u32(sm);
    const int tid = threadIdx.x, lane = tid & 31, w = tid >> 5;
    const int wmr = (w & 1) * 64, wnr = (w >> 1) * 32;
    const int bh = blockIdx.z, b = bh >> 4, h = bh & 15;
    const int t0 = blockIdx.y * 128, s0 = blockIdx.x * 128;
    const __half* gA = Qh + (size_t)(b * T_LEN + t0) * HID + h * HD;
    const __half* gB = Kh + (size_t)(b * S_LEN + s0) * HID + h * HD;

    float acc[4][4][4] = {};
    load_stage<128>(sb + 0,    gA, HID, tid);
    load_stage<128>(sb + 8192, gB, HID, tid);
    CP_COMMIT();
    load_stage<128>(sb + 16384, gA + 32, HID, tid);
    load_stage<128>(sb + 24576, gB + 32, HID, tid);
    CP_COMMIT();
    for (int s = 0; s < 2; s++) {
        if (s == 0) CP_WAIT(1);
        else CP_WAIT(0);
        __syncthreads();
        const uint32_t cur = sb + s * 16384;
        stage_compute1(cur, cur + 8192, wmr, wnr, lane, acc);
        __syncthreads();
    }

    const int mq = lane >> 2, nq = (lane & 3) * 2;
    __half* dstB = E + (size_t)bh * T_LEN * S_LEN;
    #pragma unroll
    for (int mi = 0; mi < 4; mi++)
        #pragma unroll
        for (int half = 0; half < 2; half++) {
            const int t = t0 + wmr + mi * 16 + mq + half * 8;
            float rsum = 0.f;
            #pragma unroll
            for (int nj = 0; nj < 4; nj++) {
                const int sidx = s0 + wnr + nj * 8 + nq;
                float e0 = (amask[b * S_LEN + sidx] == 0) ? 0.f
                           : __expf(acc[mi][nj][half * 2 + 0] - 4.f);
                float e1 = (amask[b * S_LEN + sidx + 1] == 0) ? 0.f
                           : __expf(acc[mi][nj][half * 2 + 1] - 4.f);
                rsum += e0 + e1;
                __half2 h2;
                h2.x = __float2half_rn(e0);
                h2.y = __float2half_rn(e1);
                *(__half2*)(dstB + (size_t)t * S_LEN + sidx) = h2;
            }
            rsum += __shfl_xor_sync(0xFFFFFFFFu, rsum, 1);
            rsum += __shfl_xor_sync(0xFFFFFFFFu, rsum, 2);
            if ((lane & 3) == 0)
                psum[wmr + mi * 16 + half * 8 + mq][w >> 1] = rsum;
        }
    __syncthreads();
    if (tid < 128) {
        const float tot = psum[tid][0] + psum[tid][1] + psum[tid][2] + psum[tid][3];
        gps[((size_t)bh * T_LEN + t0 + tid) * 32 + blockIdx.x] = tot;
    }
}

// ---------------- row-sum reduce: rs[r] = sum of 32 partials ----------------
__global__ __launch_bounds__(256)
void rowsum_reduce(const float* __restrict__ gps, float* __restrict__ rs) {
    const int r = blockIdx.x * 256 + threadIdx.x;
    const float4* p = reinterpret_cast<const float4*>(gps + (size_t)r * 32);
    float s = 0.f;
    #pragma unroll
    for (int i = 0; i < 8; i++) {
        float4 v = p[i];
        s += v.x + v.y + v.z + v.w;
    }
    rs[r] = s;
}

// ---------------- provenance = head-mean of E/rowsum ----------------
__global__ __launch_bounds__(256)
void provenance_kernel(const __half* __restrict__ E, const float* __restrict__ rs,
                       float* __restrict__ out) {
    const size_t u = (size_t)blockIdx.x * 256 + threadIdx.x;
    const int s2 = (int)(u & 2047);
    const int t  = (int)((u >> 11) & 511);
    const int b  = (int)(u >> 20);
    float s0 = 0.f, s1 = 0.f;
    #pragma unroll
    for (int h = 0; h < NH; h++) {
        const int bh = b * NH + h;
        const float inv = 1.0f / rs[bh * T_LEN + t];
        const size_t o = (((size_t)bh * T_LEN + t) * S_LEN) / 2 + s2;
        __half2 h2 = reinterpret_cast<const __half2*>(E)[o];
        s0 += __half2float(h2.x) * inv;
        s1 += __half2float(h2.y) * inv;
    }
    reinterpret_cast<float2*>(out)[u] = make_float2(s0 * (1.0f / NH), s1 * (1.0f / NH));
}

// ---------------- P·V: C[128,64] per CTA, K=4096, normalized epilogue ----------------
__global__ __launch_bounds__(256)
void pv_gemm(const __half* __restrict__ E, const __half* __restrict__ Vh,
             const float* __restrict__ rs, __half* __restrict__ attH) {
    extern __shared__ __align__(128) char sm[];
    const uint32_t sb = smem_u32(sm);
    const int tid = threadIdx.x, lane = tid & 31, w = tid >> 5;
    const int wmr = (w & 3) * 32, wnr = (w >> 2) * 32;
    const int bh = blockIdx.y, b = bh >> 4, h = bh & 15;
    const int t0 = blockIdx.x * 128;
    const __half* gA = E + ((size_t)bh * T_LEN + t0) * S_LEN;
    const __half* gB = Vh + (size_t)(b * S_LEN) * HID + h * HD;

#define PV_LOAD(st, ko) do {                                              \
    const uint32_t b_ = sb + ((st) % 3) * 12288;                          \
    load_stage<128>(b_ + 0, gA + (ko), S_LEN, tid);                       \
    load_vtile(b_ + 8192, gB + (size_t)(ko) * HID, HID, tid);             \
    CP_COMMIT();                                                          \
  } while (0)

    float acc[2][4][4] = {};
    PV_LOAD(0, 0);
    PV_LOAD(1, 32);
    const int NST = S_LEN / 32;
    for (int s = 0; s < NST; s++) {
        if (s + 2 < NST) { PV_LOAD(s + 2, (s + 2) * 32); CP_WAIT(2); }
        else if (s + 1 < NST) { CP_WAIT(1); }
        else { CP_WAIT(0); }
        __syncthreads();
        const uint32_t cur = sb + (s % 3) * 12288;
        pv_stage1<2>(cur, cur + 8192, wmr, wnr, lane, acc);
        __syncthreads();
    }
#undef PV_LOAD

    const int mq = lane >> 2, nq = (lane & 3) * 2;
    #pragma unroll
    for (int mi = 0; mi < 2; mi++)
        #pragma unroll
        for (int half = 0; half < 2; half++) {
            const int t = t0 + wmr + mi * 16 + mq + half * 8;
            const float inv = 1.0f / rs[bh * T_LEN + t];
            const size_t mo = (size_t)(b * T_LEN + t) * HID + h * HD;
            #pragma unroll
            for (int nj = 0; nj < 4; nj++) {
                const int n = wnr + nj * 8 + nq;
                __half2 h2;
                h2.x = __float2half_rn(acc[mi][nj][half * 2 + 0] * inv);
                h2.y = __float2half_rn(acc[mi][nj][half * 2 + 1] * inv);
                *(__half2*)(attH + mo + n) = h2;
            }
        }
}

// ---------------------------------------------------------------------------
extern "C" void kernel_launch(void* const* d_in, const int* in_sizes, int n_in,
                              void* d_out, int out_size) {
    const float* query  = (const float*)d_in[0];
    const float* key    = (const float*)d_in[1];
    const float* value  = (const float*)d_in[2];
    const int*   amask  = (const int*)d_in[3];
    const int*   segids = (const int*)d_in[4];
    const float* Wq = (const float*)d_in[5];
    const float* bq = (const float*)d_in[6];
    const float* Wk = (const float*)d_in[7];
    const float* bk = (const float*)d_in[8];
    const float* Wv = (const float*)d_in[9];
    const float* bv = (const float*)d_in[10];
    const float* Wo = (const float*)d_in[11];
    const float* bo = (const float*)d_in[12];
    const float* seg_emb = (const float*)d_in[13];
    float* out = (float*)d_out;

    __half *qh, *kh, *vh;
    __half *wqh, *wql, *wkh, *wvh, *woh;
    __half *Qh, *Kh, *Vh, *E, *ah;
    float *ps, *rs;
    cudaGetSymbolAddress((void**)&qh, g_qh);
    cudaGetSymbolAddress((void**)&kh, g_kh);
    cudaGetSymbolAddress((void**)&vh, g_vh);
    cudaGetSymbolAddress((void**)&wqh, g_wqh); cudaGetSymbolAddress((void**)&wql, g_wql);
    cudaGetSymbolAddress((void**)&wkh, g_wkh);
    cudaGetSymbolAddress((void**)&wvh, g_wvh);
    cudaGetSymbolAddress((void**)&woh, g_woh);
    cudaGetSymbolAddress((void**)&Qh, g_Qh);
    cudaGetSymbolAddress((void**)&Kh, g_Kh);
    cudaGetSymbolAddress((void**)&Vh, g_Vh);
    cudaGetSymbolAddress((void**)&E, g_E);
    cudaGetSymbolAddress((void**)&ps, g_ps);
    cudaGetSymbolAddress((void**)&rs, g_rs);
    cudaGetSymbolAddress((void**)&ah, g_ah);

    cudaFuncSetAttribute(proj2q, cudaFuncAttributeMaxDynamicSharedMemorySize, 73728);
    cudaFuncSetAttribute(proj_kv, cudaFuncAttributeMaxDynamicSharedMemorySize, 49152);
    cudaFuncSetAttribute(proj_o, cudaFuncAttributeMaxDynamicSharedMemorySize, 49152);
    cudaFuncSetAttribute(scores_exp, cudaFuncAttributeMaxDynamicSharedMemorySize, 32768);
    cudaFuncSetAttribute(pv_gemm, cudaFuncAttributeMaxDynamicSharedMemorySize, 36864);

    // fused conversions
    conv_h_all<<<69632, 256>>>(query, key, value, qh, kh, vh);
    conv_wT_all<<<dim3(32, 32, 4), dim3(32, 8)>>>(Wq, Wk, Wv, Wo, wqh, wql, wkh, wvh, woh);

    // projections (K and V merged into one homogeneous launch)
    proj2q<<<dim3(8, 16), 256, 73728>>>(qh, wqh, wql, bq, Qh);
    proj_kv<<<dim3(8, 256), 256, 49152>>>(kh, vh, wkh, wvh, bk, bv, segids, seg_emb, Kh, Vh);

    // fused scores+exp (single launch), deterministic row-sum reduction
    scores_exp<<<dim3(32, 4, NBH), 256, 32768>>>(Qh, Kh, amask, E, ps);
    rowsum_reduce<<<NBH * T_LEN / 256, 256>>>(ps, rs);

    // provenance + attended
    provenance_kernel<<<16384, 256>>>(E, rs, out + (size_t)2048 * HID);
    pv_gemm<<<dim3(4, 64), 256, 36864>>>(E, Vh, rs, ah);

    // output projection -> d_out
    proj_o<<<dim3(8, 16), 256, 49152>>>(ah, woh, bo, out);
}